// round 12
// baseline (speedup 1.0000x reference)
#include <cuda_runtime.h>
#include <math.h>

#define BATCH 8
#define NVERT 8192
#define NPD 64
#define NSAMP (NPD*NPD)      // 4096
#define CH 128               // chunks (blocks) per batch
#define JCHUNK (NVERT/CH)    // 64 vertices per block
#define NTHR 128
#define STR 68               // u64 row stride (conflict-free frag gather)

// ---- device scratch (no allocations allowed) ----
__device__ float4   g_stats[BATCH*CH];
__device__ float    g_partial[BATCH*CH*NSAMP];  // 16.8 MB
__device__ float    g_K[BATCH*NSAMP];
__device__ float    g_ssum[BATCH*CH];
__device__ unsigned g_cntA[BATCH];
__device__ unsigned g_cntB[BATCH];
__device__ unsigned g_cntC[BATCH];

__device__ __forceinline__ float ex2f(float x) {
    float y; asm("ex2.approx.ftz.f32 %0, %1;" : "=f"(y) : "f"(x)); return y;
}
// pack (ve -> low bf16, vo -> high bf16), single precision plane
__device__ __forceinline__ unsigned pack_pair(float ve, float vo) {
    unsigned r;
    asm("cvt.rn.bf16x2.f32 %0, %1, %2;" : "=r"(r) : "f"(vo), "f"(ve));
    return r;
}
__device__ __forceinline__ void mma_bf16(float* d, const unsigned* a, unsigned b0, unsigned b1) {
    asm("mma.sync.aligned.m16n8k16.row.col.f32.bf16.bf16.f32 "
        "{%0,%1,%2,%3}, {%4,%5,%6,%7}, {%8,%9}, {%0,%1,%2,%3};"
        : "+f"(d[0]), "+f"(d[1]), "+f"(d[2]), "+f"(d[3])
        : "r"(a[0]), "r"(a[1]), "r"(a[2]), "r"(a[3]), "r"(b0), "r"(b1));
}
__device__ __forceinline__ void spin_until(volatile unsigned* p, unsigned v) {
    while (*p < v) { }
}

// ==================== single fused persistent kernel ====================
// grid = 1024 blocks (batch = blk>>7, chunk = blk&127), 128 threads (4 warps).
// ~7 blocks/SM co-resident (capacity 8 at 20 KB smem, 64 regs).
__global__ void __launch_bounds__(NTHR, 8) k_fused(const float* __restrict__ T,
                                                   const float* __restrict__ S,
                                                   float* __restrict__ out)
{
    // bf16 planes for 32 kpairs: u64[gi][c], gi(kp)=(kp>>3)*4+(kp&3), hf=(kp>>2)&1
    __shared__ __align__(16) unsigned long long sAh[16*STR];   // 8.5 KB
    __shared__ __align__(16) unsigned long long sBh[16*STR];   // 8.5 KB
    __shared__ __align__(16) float2 sT[JCHUNK];                // 0.5 KB
    __shared__ __align__(16) float4 s4[NTHR];                  // 2 KB
    __shared__ float  sG[NPD];
    __shared__ float4 sW[2];
    __shared__ float  sKx, sCoeff, sInv;
    __shared__ int    sIsLast;

    const int tid  = threadIdx.x;
    const int wid  = tid >> 5;
    const int lane = tid & 31;
    const int bb   = blockIdx.x >> 7;
    const int ch   = blockIdx.x & 127;

    // ---- stage T chunk (64 verts) + grid ----
    if (tid < 32)
        ((float4*)sT)[tid] = ((const float4*)(T + (size_t)(bb * NVERT + ch * JCHUNK) * 2))[tid];
    if (tid >= 64) sG[tid - 64] = S[(tid - 64) * 2 + 1];   // S[0,c,1] = g[c] exactly
    __syncthreads();

    // ================= Phase A: chunk stats + sigma =================
    {
        if (tid < 64) {
            float2 v0 = sT[tid];
            float sx = v0.x, sy = v0.y;
            float sxx = v0.x * v0.x, syy = v0.y * v0.y;
            #pragma unroll
            for (int o = 16; o; o >>= 1) {
                sx  += __shfl_xor_sync(~0u, sx,  o);
                sxx += __shfl_xor_sync(~0u, sxx, o);
                sy  += __shfl_xor_sync(~0u, sy,  o);
                syy += __shfl_xor_sync(~0u, syy, o);
            }
            if (lane == 0) sW[wid] = make_float4(sx, sxx, sy, syy);
        }
        __syncthreads();
        if (tid == 0) {
            float4 r = sW[0];
            r.x += sW[1].x; r.y += sW[1].y; r.z += sW[1].z; r.w += sW[1].w;
            g_stats[blockIdx.x] = r;
            __threadfence();
            atomicAdd(&g_cntA[bb], 1u);
            spin_until(&g_cntA[bb], CH);
            __threadfence();
        }
        __syncthreads();
    }
    if (tid < 32) {
        float sx = 0.f, sxx = 0.f, sy = 0.f, syy = 0.f;
        #pragma unroll
        for (int k = 0; k < 4; ++k) {
            float4 st = __ldcg(&g_stats[bb * CH + k * 32 + tid]);
            sx += st.x; sxx += st.y; sy += st.z; syy += st.w;
        }
        #pragma unroll
        for (int o = 16; o; o >>= 1) {
            sx  += __shfl_xor_sync(~0u, sx,  o);
            sxx += __shfl_xor_sync(~0u, sxx, o);
            sy  += __shfl_xor_sync(~0u, sy,  o);
            syy += __shfl_xor_sync(~0u, syy, o);
        }
        if (tid == 0) {
            const double n = (double)NVERT;
            double vx = ((double)sxx - (double)sx*(double)sx/n) / (n - 1.0);
            double vy = ((double)syy - (double)sy*(double)sy/n) / (n - 1.0);
            if (vx < 0.0) vx = 0.0;
            if (vy < 0.0) vy = 0.0;
            double sigma = 0.5 * (sqrt(vx) + sqrt(vy));
            const double bd = 1.0 / 63.0;
            if (sigma < bd) sigma = bd;
            const double p  = exp2(13.0 / 3.0);   // CN=-p/2, CF=p/(2pi)
            const double s2 = sigma * sigma;
            sKx    = (float)((-0.5 * p) / s2 * 1.4426950408889634);
            sCoeff = (float)((p / (2.0 * M_PI)) / s2 / (double)NVERT);
        }
    }
    __syncthreads();
    const float kx = sKx;

    // ================= Phase B: fill then barrier-free MMA GEMM =================
    // ---- fill: 32 kpairs x 64 cols x (A,B); 64 independent ex2 per thread ----
    #pragma unroll 4
    for (int i = 0; i < 16; ++i) {
        const int slot = tid + i * 128;
        const int kp = slot >> 6, c = slot & 63;
        const float2 t0 = sT[2 * kp];
        const float2 t1 = sT[2 * kp + 1];
        const float gv = sG[c];
        const int gi = ((kp >> 3) * 4 + (kp & 3)) * STR + c;
        const int hf = (kp >> 2) & 1;
        float d0 = gv - t0.x, d1 = gv - t1.x;
        ((unsigned*)sAh)[gi * 2 + hf] =
            pack_pair(ex2f(kx * (d0 * d0)), ex2f(kx * (d1 * d1)));
        d0 = gv - t0.y; d1 = gv - t1.y;
        ((unsigned*)sBh)[gi * 2 + hf] =
            pack_pair(ex2f(kx * (d0 * d0)), ex2f(kx * (d1 * d1)));
    }
    __syncthreads();

    // ---- barrier-free GEMM: 4 k16-steps, single bf16 pass ----
    float dacc[8][4];
    #pragma unroll
    for (int nt = 0; nt < 8; ++nt)
        #pragma unroll
        for (int i = 0; i < 4; ++i) dacc[nt][i] = 0.f;

    const int g = lane >> 2, q = lane & 3;
    const int r0 = wid * 16 + g, r1 = r0 + 8;

    #pragma unroll
    for (int s = 0; s < 4; ++s) {
        const int row = (s * 4 + q) * STR;
        const unsigned long long a01 = sAh[row + r0];
        const unsigned long long a23 = sAh[row + r1];
        unsigned ah[4] = { (unsigned)a01, (unsigned)a23,
                           (unsigned)(a01 >> 32), (unsigned)(a23 >> 32) };
        #pragma unroll
        for (int nt = 0; nt < 8; ++nt) {
            const unsigned long long bh = sBh[row + nt * 8 + g];
            mma_bf16(dacc[nt], ah, (unsigned)bh, (unsigned)(bh >> 32));
        }
    }

    // write this block's 64x64 partial (rows r0/r1, cols nt*8 + 2q)
    {
        float* outp = g_partial + (size_t)blockIdx.x * NSAMP;
        #pragma unroll
        for (int nt = 0; nt < 8; ++nt) {
            const int n0 = nt * 8 + 2 * q;
            *(float2*)(outp + r0 * NPD + n0) = make_float2(dacc[nt][0], dacc[nt][1]);
            *(float2*)(outp + r1 * NPD + n0) = make_float2(dacc[nt][2], dacc[nt][3]);
        }
    }
    __threadfence();
    __syncthreads();
    if (tid == 0) {
        atomicAdd(&g_cntB[bb], 1u);
        spin_until(&g_cntB[bb], CH);
        __threadfence();
    }
    __syncthreads();

    // ================= Phase C: cooperative reduce + segment sums =================
    // Block (bb,ch) reduces image float4 positions [ch*8, ch*8+8) over 128 chunks.
    {
        const int pos = ch * 8 + (tid & 7);
        const int cg  = tid >> 3;                      // 0..15 -> 8 chunks each
        const float4* base = (const float4*)g_partial + (size_t)bb * CH * 1024 + pos;
        float4 s = make_float4(0.f, 0.f, 0.f, 0.f);
        #pragma unroll
        for (int c = 0; c < 8; ++c) {
            float4 v = __ldcg(base + (size_t)(cg * 8 + c) * 1024);
            s.x += v.x; s.y += v.y; s.z += v.z; s.w += v.w;
        }
        s4[tid] = s;
        __syncthreads();
        if (tid < 8) {
            float4 r = s4[tid];
            #pragma unroll
            for (int k = 1; k < 16; ++k) {
                float4 v = s4[tid + k * 8];
                r.x += v.x; r.y += v.y; r.z += v.z; r.w += v.w;
            }
            const float cf = sCoeff;
            r.x *= cf; r.y *= cf; r.z *= cf; r.w *= cf;
            ((float4*)g_K)[bb * 1024 + ch * 8 + tid] = r;
            float ls = r.x + r.y + r.z + r.w;
            #pragma unroll
            for (int o = 4; o; o >>= 1) ls += __shfl_xor_sync(0xFFu, ls, o);
            if (tid == 0) g_ssum[bb * CH + ch] = ls;
        }
        __syncthreads();
    }
    if (tid == 0) {
        __threadfence();
        unsigned old = atomicAdd(&g_cntC[bb], 1u);
        sIsLast = (old == CH - 1) ? 1 : 0;
    }
    __syncthreads();
    if (!sIsLast) return;

    // ================= Finalize (one block per batch) =================
    __threadfence();
    if (tid < 32) {
        float v = 0.f;
        #pragma unroll
        for (int k = 0; k < 4; ++k) v += __ldcg(&g_ssum[bb * CH + k * 32 + tid]);
        #pragma unroll
        for (int o = 16; o; o >>= 1) v += __shfl_xor_sync(~0u, v, o);
        if (tid == 0) sInv = 1.0f / fmaxf(v, 1e-5f);
    }
    __syncthreads();
    const float inv = sInv;
    const float4* kp = (const float4*)g_K + bb * 1024;
    float4* op = (float4*)out + bb * 1024;
    #pragma unroll
    for (int k = 0; k < 8; ++k) {
        float4 v = __ldcg(kp + tid + k * NTHR);
        v.x *= inv; v.y *= inv; v.z *= inv; v.w *= inv;
        op[tid + k * NTHR] = v;
    }
    if (tid == 0) { g_cntA[bb] = 0u; g_cntB[bb] = 0u; g_cntC[bb] = 0u; }
}

extern "C" void kernel_launch(void* const* d_in, const int* in_sizes, int n_in,
                              void* d_out, int out_size)
{
    const float* T = (const float*)d_in[0];
    const float* S = (const float*)d_in[1];
    if (n_in >= 2 && in_sizes[0] == BATCH * NSAMP * 2 &&
        in_sizes[1] == BATCH * NVERT * 2) {
        T = (const float*)d_in[1];
        S = (const float*)d_in[0];
    }
    k_fused<<<BATCH * CH, NTHR>>>(T, S, (float*)d_out);
}

// round 13
// speedup vs baseline: 1.0749x; 1.0749x over previous
#include <cuda_runtime.h>
#include <math.h>

#define BATCH 8
#define NVERT 8192
#define NPD 64
#define NSAMP (NPD*NPD)      // 4096
#define CH 64                // chunks (blocks) per batch
#define JCHUNK (NVERT/CH)    // 128 vertices per block
#define NGRP 8               // reduction groups per batch
#define GRP 8                // chunks per group
#define NTHR 128
#define STR 68               // u64 row stride (conflict-free frag gather)

// ---- device scratch (no allocations allowed) ----
__device__ float    g_kx[BATCH];
__device__ float    g_coeff[BATCH];
__device__ float    g_partial[BATCH*CH*NSAMP];    // 8 MB
__device__ float    g_p1[BATCH*NGRP*NSAMP];       // 1 MB level-1 partials
__device__ unsigned g_t1[BATCH*NGRP];             // level-1 tickets
__device__ unsigned g_t2[BATCH];                  // level-2 tickets

__device__ __forceinline__ float ex2f(float x) {
    float y; asm("ex2.approx.ftz.f32 %0, %1;" : "=f"(y) : "f"(x)); return y;
}
// pack (ve -> low bf16, vo -> high bf16)
__device__ __forceinline__ unsigned pack_pair(float ve, float vo) {
    unsigned r;
    asm("cvt.rn.bf16x2.f32 %0, %1, %2;" : "=r"(r) : "f"(vo), "f"(ve));
    return r;
}
__device__ __forceinline__ void mma_bf16(float* d, const unsigned* a, unsigned b0, unsigned b1) {
    asm("mma.sync.aligned.m16n8k16.row.col.f32.bf16.bf16.f32 "
        "{%0,%1,%2,%3}, {%4,%5,%6,%7}, {%8,%9}, {%0,%1,%2,%3};"
        : "+f"(d[0]), "+f"(d[1]), "+f"(d[2]), "+f"(d[3])
        : "r"(a[0]), "r"(a[1]), "r"(a[2]), "r"(a[3]), "r"(b0), "r"(b1));
}

// ============ Kernel 1: sigma + constants (proven round-1 code) ============
__global__ void __launch_bounds__(256) k_sigma(const float* __restrict__ T) {
    int bb = blockIdx.x;
    int tid = threadIdx.x;
    const float4* t4 = (const float4*)(T + (size_t)bb * NVERT * 2);
    float sx = 0.f, sxx = 0.f, sy = 0.f, syy = 0.f;
    #pragma unroll
    for (int k = 0; k < 16; ++k) {
        float4 v = t4[tid + k * 256];            // (x0,y0,x1,y1)
        sx  += v.x + v.z;  sy  += v.y + v.w;
        sxx += v.x * v.x + v.z * v.z;
        syy += v.y * v.y + v.w * v.w;
    }
    #pragma unroll
    for (int o = 16; o; o >>= 1) {
        sx  += __shfl_xor_sync(~0u, sx,  o);
        sxx += __shfl_xor_sync(~0u, sxx, o);
        sy  += __shfl_xor_sync(~0u, sy,  o);
        syy += __shfl_xor_sync(~0u, syy, o);
    }
    __shared__ float4 sred[8];
    if ((tid & 31) == 0) sred[tid >> 5] = make_float4(sx, sxx, sy, syy);
    __syncthreads();
    if (tid == 0) {
        double Sx = 0, Sxx = 0, Sy = 0, Syy = 0;
        #pragma unroll
        for (int w = 0; w < 8; ++w) {
            float4 r = sred[w];
            Sx += r.x; Sxx += r.y; Sy += r.z; Syy += r.w;
        }
        const double n = (double)NVERT;
        double vx = (Sxx - Sx * Sx / n) / (n - 1.0);
        double vy = (Syy - Sy * Sy / n) / (n - 1.0);
        if (vx < 0.0) vx = 0.0;
        if (vy < 0.0) vy = 0.0;
        double sigma = 0.5 * (sqrt(vx) + sqrt(vy));
        const double bd = 1.0 / 63.0;
        if (sigma < bd) sigma = bd;
        const double p  = exp2(13.0 / 3.0);      // CN=-p/2, CF=p/(2pi)
        const double s2 = sigma * sigma;
        g_kx[bb]    = (float)((-0.5 * p) / s2 * 1.4426950408889634);
        g_coeff[bb] = (float)((p / (2.0 * M_PI)) / s2 / (double)NVERT);
    }
}

// ============ Kernel 2: GEMM + ticket-based hierarchical reduce ============
// grid = 512 blocks (batch = blk>>6, chunk = blk&63), 128 threads (4 warps).
// No global barriers: blocks exit after GEMM; last-of-group / last-of-batch
// blocks (by atomic ticket) perform fixed-order deterministic reductions.
__global__ void __launch_bounds__(NTHR) k_main(const float* __restrict__ T,
                                               const float* __restrict__ S,
                                               float* __restrict__ out)
{
    __shared__ __align__(16) unsigned long long sA[16*STR];   // 8.5 KB
    __shared__ __align__(16) unsigned long long sB[16*STR];   // 8.5 KB
    __shared__ __align__(16) float2 sT[JCHUNK];               // 1 KB
    __shared__ float sG[NPD];
    __shared__ float sWr[4];
    __shared__ float sInv;
    __shared__ int   sL1, sL2;

    const int tid  = threadIdx.x;
    const int wid  = tid >> 5;
    const int lane = tid & 31;
    const int bb   = blockIdx.x >> 6;
    const int ch   = blockIdx.x & 63;

    // ---- stage T chunk + grid ----
    if (tid < 64)
        ((float4*)sT)[tid] = ((const float4*)(T + (size_t)(bb * NVERT + ch * JCHUNK) * 2))[tid];
    if (tid >= 64) sG[tid - 64] = S[(tid - 64) * 2 + 1];   // S[0,c,1] = g[c] exactly
    const float kx = __ldcg(&g_kx[bb]);
    __syncthreads();

    // ================= Phase B: 2-stage fill + barrier-free single-pass MMA =================
    float dacc[8][4];
    #pragma unroll
    for (int nt = 0; nt < 8; ++nt)
        #pragma unroll
        for (int i = 0; i < 4; ++i) dacc[nt][i] = 0.f;

    const int g = lane >> 2, q = lane & 3;
    const int r0 = wid * 16 + g, r1 = r0 + 8;

    #pragma unroll
    for (int st = 0; st < 2; ++st) {
        const int jb = st * 64;
        // fill: 32 kpairs x 64 cols x (A,B); 64 independent ex2 per thread
        #pragma unroll 4
        for (int i = 0; i < 16; ++i) {
            const int slot = tid + i * 128;
            const int kp = slot >> 6, c = slot & 63;
            const float2 t0 = sT[jb + 2 * kp];
            const float2 t1 = sT[jb + 2 * kp + 1];
            const float gv = sG[c];
            const int gi = ((kp >> 3) * 4 + (kp & 3)) * STR + c;
            const int hf = (kp >> 2) & 1;
            float d0 = gv - t0.x, d1 = gv - t1.x;
            ((unsigned*)sA)[gi * 2 + hf] =
                pack_pair(ex2f(kx * (d0 * d0)), ex2f(kx * (d1 * d1)));
            d0 = gv - t0.y; d1 = gv - t1.y;
            ((unsigned*)sB)[gi * 2 + hf] =
                pack_pair(ex2f(kx * (d0 * d0)), ex2f(kx * (d1 * d1)));
        }
        __syncthreads();
        // barrier-free GEMM: 4 k16-steps
        #pragma unroll
        for (int s = 0; s < 4; ++s) {
            const int row = (s * 4 + q) * STR;
            const unsigned long long a01 = sA[row + r0];
            const unsigned long long a23 = sA[row + r1];
            unsigned ah[4] = { (unsigned)a01, (unsigned)a23,
                               (unsigned)(a01 >> 32), (unsigned)(a23 >> 32) };
            #pragma unroll
            for (int nt = 0; nt < 8; ++nt) {
                const unsigned long long bh = sB[row + nt * 8 + g];
                mma_bf16(dacc[nt], ah, (unsigned)bh, (unsigned)(bh >> 32));
            }
        }
        __syncthreads();
    }

    // ---- write this block's 64x64 partial ----
    {
        float* outp = g_partial + (size_t)blockIdx.x * NSAMP;
        #pragma unroll
        for (int nt = 0; nt < 8; ++nt) {
            const int n0 = nt * 8 + 2 * q;
            *(float2*)(outp + r0 * NPD + n0) = make_float2(dacc[nt][0], dacc[nt][1]);
            *(float2*)(outp + r1 * NPD + n0) = make_float2(dacc[nt][2], dacc[nt][3]);
        }
    }
    __threadfence();
    __syncthreads();

    // ================= Level-1 ticket: last of 8-chunk group reduces =================
    const int grp = ch >> 3;
    if (tid == 0)
        sL1 = (atomicAdd(&g_t1[bb * NGRP + grp], 1u) == GRP - 1) ? 1 : 0;
    __syncthreads();
    if (!sL1) return;                 // 7 of 8 blocks exit here
    __threadfence();

    {
        const float4* base = (const float4*)g_partial + (size_t)(bb * CH + grp * GRP) * 1024;
        float4* dst = (float4*)g_p1 + (size_t)(bb * NGRP + grp) * 1024;
        #pragma unroll
        for (int p = 0; p < 8; ++p) {
            const int pos = tid + p * 128;
            float4 s = make_float4(0.f, 0.f, 0.f, 0.f);
            #pragma unroll
            for (int c = 0; c < GRP; ++c) {      // fixed order -> deterministic
                float4 v = __ldcg(base + (size_t)c * 1024 + pos);
                s.x += v.x; s.y += v.y; s.z += v.z; s.w += v.w;
            }
            dst[pos] = s;
        }
    }
    __threadfence();
    __syncthreads();

    // ================= Level-2 ticket: last group finisher finalizes batch =================
    if (tid == 0)
        sL2 = (atomicAdd(&g_t2[bb], 1u) == NGRP - 1) ? 1 : 0;
    __syncthreads();
    if (!sL2) return;                 // 7 of 8 group-reducers exit here
    __threadfence();

    {
        const float cf = __ldcg(&g_coeff[bb]);
        const float4* p1 = (const float4*)g_p1 + (size_t)bb * NGRP * 1024;
        float4 acc[8];
        float lsum = 0.f;
        #pragma unroll
        for (int p = 0; p < 8; ++p) {
            const int pos = tid + p * 128;
            float4 s = make_float4(0.f, 0.f, 0.f, 0.f);
            #pragma unroll
            for (int gi = 0; gi < NGRP; ++gi) {   // fixed order -> deterministic
                float4 v = __ldcg(p1 + (size_t)gi * 1024 + pos);
                s.x += v.x; s.y += v.y; s.z += v.z; s.w += v.w;
            }
            s.x *= cf; s.y *= cf; s.z *= cf; s.w *= cf;
            acc[p] = s;
            lsum += s.x + s.y + s.z + s.w;
        }
        #pragma unroll
        for (int o = 16; o; o >>= 1) lsum += __shfl_xor_sync(~0u, lsum, o);
        if (lane == 0) sWr[wid] = lsum;
        __syncthreads();
        if (tid == 0) {
            float t = sWr[0] + sWr[1] + sWr[2] + sWr[3];
            sInv = 1.0f / fmaxf(t, 1e-5f);
        }
        __syncthreads();
        const float inv = sInv;
        float4* op = (float4*)out + (size_t)bb * 1024;
        #pragma unroll
        for (int p = 0; p < 8; ++p) {
            const int pos = tid + p * 128;
            float4 v = acc[p];
            v.x *= inv; v.y *= inv; v.z *= inv; v.w *= inv;
            op[pos] = v;
        }
        // reset tickets for next graph replay
        if (tid < NGRP) g_t1[bb * NGRP + tid] = 0u;
        if (tid == 0)   g_t2[bb] = 0u;
    }
}

extern "C" void kernel_launch(void* const* d_in, const int* in_sizes, int n_in,
                              void* d_out, int out_size)
{
    const float* T = (const float*)d_in[0];
    const float* S = (const float*)d_in[1];
    if (n_in >= 2 && in_sizes[0] == BATCH * NSAMP * 2 &&
        in_sizes[1] == BATCH * NVERT * 2) {
        T = (const float*)d_in[1];
        S = (const float*)d_in[0];
    }
    k_sigma<<<BATCH, 256>>>(T);
    k_main <<<BATCH * CH, NTHR>>>(T, S, (float*)d_out);
}

// round 14
// speedup vs baseline: 1.0980x; 1.0215x over previous
#include <cuda_runtime.h>
#include <math.h>

#define BATCH 8
#define NVERT 8192
#define NPD 64
#define NSAMP (NPD*NPD)      // 4096
#define CH 64                // chunks (blocks) per batch
#define JCHUNK (NVERT/CH)    // 128 vertices per block
#define NGRP 8               // reduction groups per batch
#define GRP 8                // chunks per group
#define NTHR 128
#define STR 68               // u64 row stride (conflict-free frag gather)

// ---- device scratch (no allocations allowed) ----
__device__ float    g_partial[BATCH*CH*NSAMP];    // 8 MB
__device__ float    g_p1[BATCH*NGRP*NSAMP];       // 1 MB level-1 partials
__device__ unsigned g_t1[BATCH*NGRP];             // level-1 tickets
__device__ unsigned g_t2[BATCH];                  // level-2 tickets

__device__ __forceinline__ float ex2f(float x) {
    float y; asm("ex2.approx.ftz.f32 %0, %1;" : "=f"(y) : "f"(x)); return y;
}
// pack (ve -> low bf16, vo -> high bf16)
__device__ __forceinline__ unsigned pack_pair(float ve, float vo) {
    unsigned r;
    asm("cvt.rn.bf16x2.f32 %0, %1, %2;" : "=r"(r) : "f"(vo), "f"(ve));
    return r;
}
__device__ __forceinline__ void mma_bf16(float* d, const unsigned* a, unsigned b0, unsigned b1) {
    asm("mma.sync.aligned.m16n8k16.row.col.f32.bf16.bf16.f32 "
        "{%0,%1,%2,%3}, {%4,%5,%6,%7}, {%8,%9}, {%0,%1,%2,%3};"
        : "+f"(d[0]), "+f"(d[1]), "+f"(d[2]), "+f"(d[3])
        : "r"(a[0]), "r"(a[1]), "r"(a[2]), "r"(a[3]), "r"(b0), "r"(b1));
}

// ==================== single kernel: sigma(redundant) + GEMM + ticket reduce ====================
// grid = 512 blocks (batch = blk>>6, chunk = blk&63), 128 threads (4 warps).
__global__ void __launch_bounds__(NTHR) k_main(const float* __restrict__ T,
                                               const float* __restrict__ S,
                                               float* __restrict__ out)
{
    __shared__ __align__(16) unsigned long long sA[16*STR];   // 8.5 KB
    __shared__ __align__(16) unsigned long long sB[16*STR];   // 8.5 KB
    __shared__ __align__(16) float2 sT[JCHUNK];               // 1 KB
    __shared__ float  sG[NPD];
    __shared__ float4 sW[4];
    __shared__ float  sKx, sCoeff, sInv;
    __shared__ float  sWr[4];
    __shared__ int    sL1, sL2;

    const int tid  = threadIdx.x;
    const int wid  = tid >> 5;
    const int lane = tid & 31;
    const int bb   = blockIdx.x >> 6;
    const int ch   = blockIdx.x & 63;

    // ---- stage T chunk + grid ----
    if (tid < 64)
        ((float4*)sT)[tid] = ((const float4*)(T + (size_t)(bb * NVERT + ch * JCHUNK) * 2))[tid];
    if (tid >= 64) sG[tid - 64] = S[(tid - 64) * 2 + 1];   // S[0,c,1] = g[c] exactly

    // ---- redundant per-block sigma: every block reads full batch T (L2-resident) ----
    // Fixed-order reduction -> bitwise-identical sigma in all 64 blocks of a batch.
    {
        const float4* t4 = (const float4*)(T + (size_t)bb * NVERT * 2);  // 4096 float4
        float sx = 0.f, sxx = 0.f, sy = 0.f, syy = 0.f;
        #pragma unroll 8
        for (int k = 0; k < 32; ++k) {
            float4 v = __ldg(t4 + tid + k * 128);        // (x0,y0,x1,y1)
            sx  += v.x + v.z;  sy  += v.y + v.w;
            sxx += v.x * v.x + v.z * v.z;
            syy += v.y * v.y + v.w * v.w;
        }
        #pragma unroll
        for (int o = 16; o; o >>= 1) {
            sx  += __shfl_xor_sync(~0u, sx,  o);
            sxx += __shfl_xor_sync(~0u, sxx, o);
            sy  += __shfl_xor_sync(~0u, sy,  o);
            syy += __shfl_xor_sync(~0u, syy, o);
        }
        if (lane == 0) sW[wid] = make_float4(sx, sxx, sy, syy);
        __syncthreads();
        if (tid == 0) {
            double Sx = 0, Sxx = 0, Sy = 0, Syy = 0;
            #pragma unroll
            for (int w = 0; w < 4; ++w) {
                float4 r = sW[w];
                Sx += r.x; Sxx += r.y; Sy += r.z; Syy += r.w;
            }
            const double n = (double)NVERT;
            double vx = (Sxx - Sx * Sx / n) / (n - 1.0);
            double vy = (Syy - Sy * Sy / n) / (n - 1.0);
            if (vx < 0.0) vx = 0.0;
            if (vy < 0.0) vy = 0.0;
            double sigma = 0.5 * (sqrt(vx) + sqrt(vy));
            const double bd = 1.0 / 63.0;
            if (sigma < bd) sigma = bd;
            const double p  = exp2(13.0 / 3.0);      // CN=-p/2, CF=p/(2pi)
            const double s2 = sigma * sigma;
            sKx    = (float)((-0.5 * p) / s2 * 1.4426950408889634);
            sCoeff = (float)((p / (2.0 * M_PI)) / s2 / (double)NVERT);
        }
        __syncthreads();
    }
    const float kx = sKx;

    // ================= Phase B: 2-stage fill + barrier-free single-pass MMA =================
    float dacc[8][4];
    #pragma unroll
    for (int nt = 0; nt < 8; ++nt)
        #pragma unroll
        for (int i = 0; i < 4; ++i) dacc[nt][i] = 0.f;

    const int g = lane >> 2, q = lane & 3;
    const int r0 = wid * 16 + g, r1 = r0 + 8;

    #pragma unroll
    for (int st = 0; st < 2; ++st) {
        const int jb = st * 64;
        // fill: 32 kpairs x 64 cols x (A,B); 64 independent ex2 per thread
        #pragma unroll 4
        for (int i = 0; i < 16; ++i) {
            const int slot = tid + i * 128;
            const int kp = slot >> 6, c = slot & 63;
            const float2 t0 = sT[jb + 2 * kp];
            const float2 t1 = sT[jb + 2 * kp + 1];
            const float gv = sG[c];
            const int gi = ((kp >> 3) * 4 + (kp & 3)) * STR + c;
            const int hf = (kp >> 2) & 1;
            float d0 = gv - t0.x, d1 = gv - t1.x;
            ((unsigned*)sA)[gi * 2 + hf] =
                pack_pair(ex2f(kx * (d0 * d0)), ex2f(kx * (d1 * d1)));
            d0 = gv - t0.y; d1 = gv - t1.y;
            ((unsigned*)sB)[gi * 2 + hf] =
                pack_pair(ex2f(kx * (d0 * d0)), ex2f(kx * (d1 * d1)));
        }
        __syncthreads();
        // barrier-free GEMM: 4 k16-steps
        #pragma unroll
        for (int s = 0; s < 4; ++s) {
            const int row = (s * 4 + q) * STR;
            const unsigned long long a01 = sA[row + r0];
            const unsigned long long a23 = sA[row + r1];
            unsigned ah[4] = { (unsigned)a01, (unsigned)a23,
                               (unsigned)(a01 >> 32), (unsigned)(a23 >> 32) };
            #pragma unroll
            for (int nt = 0; nt < 8; ++nt) {
                const unsigned long long bh = sB[row + nt * 8 + g];
                mma_bf16(dacc[nt], ah, (unsigned)bh, (unsigned)(bh >> 32));
            }
        }
        __syncthreads();
    }

    // ---- write this block's 64x64 partial ----
    {
        float* outp = g_partial + (size_t)blockIdx.x * NSAMP;
        #pragma unroll
        for (int nt = 0; nt < 8; ++nt) {
            const int n0 = nt * 8 + 2 * q;
            *(float2*)(outp + r0 * NPD + n0) = make_float2(dacc[nt][0], dacc[nt][1]);
            *(float2*)(outp + r1 * NPD + n0) = make_float2(dacc[nt][2], dacc[nt][3]);
        }
    }
    __threadfence();
    __syncthreads();

    // ================= Level-1 ticket: last of 8-chunk group reduces =================
    const int grp = ch >> 3;
    if (tid == 0)
        sL1 = (atomicAdd(&g_t1[bb * NGRP + grp], 1u) == GRP - 1) ? 1 : 0;
    __syncthreads();
    if (!sL1) return;                 // 7 of 8 blocks exit here
    __threadfence();

    {
        const float4* base = (const float4*)g_partial + (size_t)(bb * CH + grp * GRP) * 1024;
        float4* dst = (float4*)g_p1 + (size_t)(bb * NGRP + grp) * 1024;
        #pragma unroll
        for (int p = 0; p < 8; ++p) {
            const int pos = tid + p * 128;
            float4 s = make_float4(0.f, 0.f, 0.f, 0.f);
            #pragma unroll
            for (int c = 0; c < GRP; ++c) {      // fixed order -> deterministic
                float4 v = __ldcg(base + (size_t)c * 1024 + pos);
                s.x += v.x; s.y += v.y; s.z += v.z; s.w += v.w;
            }
            dst[pos] = s;
        }
    }
    __threadfence();
    __syncthreads();

    // ================= Level-2 ticket: last group finisher finalizes batch =================
    if (tid == 0)
        sL2 = (atomicAdd(&g_t2[bb], 1u) == NGRP - 1) ? 1 : 0;
    __syncthreads();
    if (!sL2) return;                 // 7 of 8 group-reducers exit here
    __threadfence();

    {
        const float cf = sCoeff;
        const float4* p1 = (const float4*)g_p1 + (size_t)bb * NGRP * 1024;
        float4 acc[8];
        float lsum = 0.f;
        #pragma unroll
        for (int p = 0; p < 8; ++p) {
            const int pos = tid + p * 128;
            float4 s = make_float4(0.f, 0.f, 0.f, 0.f);
            #pragma unroll
            for (int gi = 0; gi < NGRP; ++gi) {   // fixed order -> deterministic
                float4 v = __ldcg(p1 + (size_t)gi * 1024 + pos);
                s.x += v.x; s.y += v.y; s.z += v.z; s.w += v.w;
            }
            s.x *= cf; s.y *= cf; s.z *= cf; s.w *= cf;
            acc[p] = s;
            lsum += s.x + s.y + s.z + s.w;
        }
        #pragma unroll
        for (int o = 16; o; o >>= 1) lsum += __shfl_xor_sync(~0u, lsum, o);
        if (lane == 0) sWr[wid] = lsum;
        __syncthreads();
        if (tid == 0) {
            float t = sWr[0] + sWr[1] + sWr[2] + sWr[3];
            sInv = 1.0f / fmaxf(t, 1e-5f);
        }
        __syncthreads();
        const float inv = sInv;
        float4* op = (float4*)out + (size_t)bb * 1024;
        #pragma unroll
        for (int p = 0; p < 8; ++p) {
            const int pos = tid + p * 128;
            float4 v = acc[p];
            v.x *= inv; v.y *= inv; v.z *= inv; v.w *= inv;
            op[pos] = v;
        }
        // reset tickets for next graph replay
        if (tid < NGRP) g_t1[bb * NGRP + tid] = 0u;
        if (tid == 0)   g_t2[bb] = 0u;
    }
}

extern "C" void kernel_launch(void* const* d_in, const int* in_sizes, int n_in,
                              void* d_out, int out_size)
{
    const float* T = (const float*)d_in[0];
    const float* S = (const float*)d_in[1];
    if (n_in >= 2 && in_sizes[0] == BATCH * NSAMP * 2 &&
        in_sizes[1] == BATCH * NVERT * 2) {
        T = (const float*)d_in[1];
        S = (const float*)d_in[0];
    }
    k_main<<<BATCH * CH, NTHR>>>(T, S, (float*)d_out);
}